// round 1
// baseline (speedup 1.0000x reference)
#include <cuda_runtime.h>
#include <cuda_bf16.h>

#define NN 50000
#define NE 800000
#define DD 256
#define EPSBN 1e-5f
#define SLOPE 0.01f

// ---------------- static device scratch (no allocations allowed) ----------------
__device__ float g_deg[NN];
__device__ float g_dinv[NN];
__device__ int   g_cnt[NN];
__device__ int   g_rowptr[NN + 1];
__device__ int   g_wr[NN];
__device__ int   g_col[NE];
__device__ float g_val[NE];
__device__ float g_y[NN * DD];   // GEMM output
__device__ float g_z[NN * DD];   // SpMM output (pre-BN, incl. bias)
__device__ float g_sum[DD];
__device__ float g_sumsq[DD];
__device__ float g_a[DD];        // BN affine scale  (gamma * rstd)
__device__ float g_b2[DD];       // BN affine shift  (beta - mu * scale)

// ---------------- preprocessing: gcn_norm + CSR build ----------------
__global__ void k_init() {
    int i = blockIdx.x * blockDim.x + threadIdx.x;
    if (i < NN) { g_deg[i] = 1.0f; g_cnt[i] = 0; }  // self-loop weight 1
}

__global__ void k_deg(const int* __restrict__ dst, const float* __restrict__ ew) {
    int e = blockIdx.x * blockDim.x + threadIdx.x;
    if (e < NE) {
        int d = dst[e];
        atomicAdd(&g_deg[d], ew[e]);
        atomicAdd(&g_cnt[d], 1);
    }
}

__global__ void k_dinv() {
    int i = blockIdx.x * blockDim.x + threadIdx.x;
    if (i < NN) g_dinv[i] = rsqrtf(g_deg[i]);   // deg >= 1 always
}

// single-block exclusive scan of g_cnt -> g_rowptr (and g_wr copy)
__global__ void k_scan() {
    __shared__ int tsum[1024];
    int t = threadIdx.x;
    const int CH = (NN + 1023) / 1024;
    int beg = t * CH;
    int end = beg + CH; if (end > NN) end = NN;
    int s = 0;
    for (int i = beg; i < end; i++) s += g_cnt[i];
    tsum[t] = s;
    __syncthreads();
    for (int off = 1; off < 1024; off <<= 1) {
        int v = (t >= off) ? tsum[t - off] : 0;
        __syncthreads();
        tsum[t] += v;
        __syncthreads();
    }
    int run = (t == 0) ? 0 : tsum[t - 1];
    for (int i = beg; i < end; i++) {
        g_rowptr[i] = run; g_wr[i] = run;
        run += g_cnt[i];
    }
    if (t == 1023) g_rowptr[NN] = run;  // == NE
}

__global__ void k_scatter(const int* __restrict__ src, const int* __restrict__ dst,
                          const float* __restrict__ ew) {
    int e = blockIdx.x * blockDim.x + threadIdx.x;
    if (e < NE) {
        int s = src[e], d = dst[e];
        int pos = atomicAdd(&g_wr[d], 1);
        g_col[pos] = s;
        g_val[pos] = g_dinv[s] * ew[e] * g_dinv[d];
    }
}

// ---------------- first GEMM: y = h(N,6) @ W1(6,256) ----------------
__global__ void k_gemm1(const float* __restrict__ h, const float* __restrict__ W1) {
    __shared__ float sW[6 * DD];
    __shared__ float sh[64 * 6];
    int t = threadIdx.x;
    int r0 = blockIdx.x * 64;
    for (int i = t; i < 6 * DD; i += 256) sW[i] = W1[i];
    for (int i = t; i < 64 * 6; i += 256) {
        int r = r0 + i / 6;
        sh[i] = (r < NN) ? h[r * 6 + (i % 6)] : 0.0f;
    }
    __syncthreads();
    for (int rr = 0; rr < 64; rr++) {
        int r = r0 + rr;
        if (r >= NN) break;
        float acc = 0.0f;
#pragma unroll
        for (int k = 0; k < 6; k++) acc = fmaf(sh[rr * 6 + k], sW[k * DD + t], acc);
        g_y[r * DD + t] = acc;
    }
}

// ---------------- middle/last GEMM: y = act(z) @ W ----------------
// act(v, k) = leaky_relu(v * g_a[k] + g_b2[k])  (fused BN-apply + leakyReLU)
#define BM 64
#define BN 64
#define BK 16
__global__ void __launch_bounds__(256) k_gemm(const float* __restrict__ W) {
    __shared__ __align__(16) float As[BK][68];
    __shared__ __align__(16) float Bs[BK][64];
    int r0 = blockIdx.x * BM, c0 = blockIdx.y * BN;
    int t = threadIdx.x;
    int arow = t >> 2, akq = t & 3;
    int bk = t >> 4, bcq = t & 15;
    int rl = (t >> 4) << 2, cl = (t & 15) << 2;
    float acc[4][4] = {};
    for (int k0 = 0; k0 < DD; k0 += BK) {
        // A tile: rows r0..r0+63, cols k0..k0+15, with fused BN+leaky
        int gr = r0 + arow;
        float4 av = make_float4(0.f, 0.f, 0.f, 0.f);
        if (gr < NN) av = *(const float4*)&g_z[gr * DD + k0 + akq * 4];
        float vv[4] = {av.x, av.y, av.z, av.w};
#pragma unroll
        for (int j = 0; j < 4; j++) {
            int kg = k0 + akq * 4 + j;
            float v = fmaf(vv[j], g_a[kg], g_b2[kg]);
            v = (v >= 0.f) ? v : SLOPE * v;
            As[akq * 4 + j][arow] = v;
        }
        // B tile
        *(float4*)&Bs[bk][bcq * 4] = *(const float4*)&W[(k0 + bk) * DD + c0 + bcq * 4];
        __syncthreads();
#pragma unroll
        for (int kk = 0; kk < BK; kk++) {
            float4 a4 = *(const float4*)&As[kk][rl];
            float4 b4 = *(const float4*)&Bs[kk][cl];
            float ar[4] = {a4.x, a4.y, a4.z, a4.w};
            float br[4] = {b4.x, b4.y, b4.z, b4.w};
#pragma unroll
            for (int i = 0; i < 4; i++)
#pragma unroll
                for (int j = 0; j < 4; j++)
                    acc[i][j] = fmaf(ar[i], br[j], acc[i][j]);
        }
        __syncthreads();
    }
#pragma unroll
    for (int i = 0; i < 4; i++) {
        int gr = r0 + rl + i;
        if (gr >= NN) continue;
        float4 o = make_float4(acc[i][0], acc[i][1], acc[i][2], acc[i][3]);
        *(float4*)&g_y[gr * DD + c0 + cl] = o;
    }
}

// ---------------- SpMM (CSR gather by dst) + bias ----------------
// out[i][c] = dinv[i]^2 * y[i][c] + sum_e val[e]*y[col[e]][c] + bias[c]
__global__ void k_spmm(const float* __restrict__ bias, float* __restrict__ out_opt) {
    int i = blockIdx.x;
    int c = threadIdx.x;
    int beg = g_rowptr[i], end = g_rowptr[i + 1];
    float di = g_dinv[i];
    float acc = di * di * g_y[i * DD + c];
    __shared__ int   scol[64];
    __shared__ float sval[64];
    for (int p = beg; p < end; p += 64) {
        int m = end - p; if (m > 64) m = 64;
        if (c < m) { scol[c] = g_col[p + c]; sval[c] = g_val[p + c]; }
        __syncthreads();
        for (int j = 0; j < m; j++)
            acc = fmaf(sval[j], g_y[scol[j] * DD + c], acc);
        __syncthreads();
    }
    float* o = out_opt ? out_opt : g_z;
    o[i * DD + c] = acc + bias[c];
}

// ---------------- BN stats ----------------
__global__ void k_zero_stats() {
    int c = threadIdx.x;
    g_sum[c] = 0.f; g_sumsq[c] = 0.f;
}

__global__ void k_stats() {
    int c = threadIdx.x;
    float s = 0.f, s2 = 0.f;
    for (int r = blockIdx.x; r < NN; r += gridDim.x) {
        float v = g_z[r * DD + c];
        s += v; s2 += v * v;
    }
    atomicAdd(&g_sum[c], s);
    atomicAdd(&g_sumsq[c], s2);
}

__global__ void k_finalize(const float* __restrict__ gamma, const float* __restrict__ beta) {
    int c = threadIdx.x;
    float mu  = g_sum[c]   * (1.0f / NN);
    float ex2 = g_sumsq[c] * (1.0f / NN);
    float var = ex2 - mu * mu;
    float a = gamma[c] * rsqrtf(var + EPSBN);
    g_a[c]  = a;
    g_b2[c] = beta[c] - mu * a;
}

// ---------------- launch ----------------
extern "C" void kernel_launch(void* const* d_in, const int* in_sizes, int n_in,
                              void* d_out, int out_size) {
    const float* h   = (const float*)d_in[0];
    const int*   ei  = (const int*)  d_in[1];
    const float* ew  = (const float*)d_in[2];
    const float* W1  = (const float*)d_in[3];
    const float* b1  = (const float*)d_in[4];
    const float* g1  = (const float*)d_in[5];
    const float* be1 = (const float*)d_in[6];
    const float* Wm  = (const float*)d_in[7];
    const float* bm  = (const float*)d_in[8];
    const float* gm  = (const float*)d_in[9];
    const float* bem = (const float*)d_in[10];
    const float* Wl  = (const float*)d_in[11];
    const float* bl  = (const float*)d_in[12];
    const int* src = ei;
    const int* dst = ei + NE;

    // preprocessing: norm + CSR
    k_init<<<(NN + 255) / 256, 256>>>();
    k_deg<<<(NE + 255) / 256, 256>>>(dst, ew);
    k_dinv<<<(NN + 255) / 256, 256>>>();
    k_scan<<<1, 1024>>>();
    k_scatter<<<(NE + 255) / 256, 256>>>(src, dst, ew);

    dim3 ggrid((NN + BM - 1) / BM, DD / BN);

    // layer 1
    k_gemm1<<<(NN + 63) / 64, 256>>>(h, W1);
    k_spmm<<<NN, DD>>>(b1, nullptr);
    k_zero_stats<<<1, DD>>>();
    k_stats<<<256, DD>>>();
    k_finalize<<<1, DD>>>(g1, be1);

    // 6 middle layers
    for (int i = 0; i < 6; i++) {
        k_gemm<<<ggrid, 256>>>(Wm + i * DD * DD);
        k_spmm<<<NN, DD>>>(bm + i * DD, nullptr);
        k_zero_stats<<<1, DD>>>();
        k_stats<<<256, DD>>>();
        k_finalize<<<1, DD>>>(gm + i * DD, bem + i * DD);
    }

    // last layer -> d_out
    k_gemm<<<ggrid, 256>>>(Wl);
    k_spmm<<<NN, DD>>>(bl, (float*)d_out);
}

// round 5
// speedup vs baseline: 1.2493x; 1.2493x over previous
#include <cuda_runtime.h>
#include <cuda_bf16.h>
#include <cstdint>

#define NN 50000
#define NE 800000
#define DD 256
#define EPSBN 1e-5f
#define SLOPE 0.01f

// ---------------- static device scratch ----------------
__device__ float g_deg[NN];
__device__ float g_dinv[NN];
__device__ int   g_cnt[NN];
__device__ int   g_rowptr[NN + 1];
__device__ int   g_wr[NN];
__device__ int   g_col[NE];
__device__ float g_val[NE];
__device__ float g_y[NN * DD];                 // GEMM output (fp32)
__device__ float g_z[NN * DD];                 // SpMM output (pre-BN)
__device__ __nv_bfloat16 g_ah[NN * DD];        // split activations hi
__device__ __nv_bfloat16 g_al[NN * DD];        // split activations lo
__device__ __nv_bfloat16 g_wh[7 * DD * DD];    // split transposed weights hi  [l][n][k]
__device__ __nv_bfloat16 g_wl[7 * DD * DD];    // split transposed weights lo
__device__ float g_sum[DD];
__device__ float g_sumsq[DD];
__device__ float g_a[DD];                      // BN affine scale
__device__ float g_b2[DD];                     // BN affine shift

__device__ __forceinline__ void mma16816(float* c, const uint32_t* a, const uint32_t* b) {
    asm volatile(
        "mma.sync.aligned.m16n8k16.row.col.f32.bf16.bf16.f32 "
        "{%0,%1,%2,%3}, {%4,%5,%6,%7}, {%8,%9}, {%0,%1,%2,%3};"
        : "+f"(c[0]), "+f"(c[1]), "+f"(c[2]), "+f"(c[3])
        : "r"(a[0]), "r"(a[1]), "r"(a[2]), "r"(a[3]), "r"(b[0]), "r"(b[1]));
}

// ---------------- preprocessing: gcn_norm + CSR build (R1-verified) ----------------
__global__ void k_init() {
    int i = blockIdx.x * blockDim.x + threadIdx.x;
    if (i < NN) { g_deg[i] = 1.0f; g_cnt[i] = 0; }
}
__global__ void k_deg(const int* __restrict__ dst, const float* __restrict__ ew) {
    int e = blockIdx.x * blockDim.x + threadIdx.x;
    if (e < NE) {
        int d = dst[e];
        atomicAdd(&g_deg[d], ew[e]);
        atomicAdd(&g_cnt[d], 1);
    }
}
__global__ void k_dinv() {
    int i = blockIdx.x * blockDim.x + threadIdx.x;
    if (i < NN) g_dinv[i] = rsqrtf(g_deg[i]);
}
__global__ void k_scan() {
    __shared__ int tsum[1024];
    int t = threadIdx.x;
    const int CH = (NN + 1023) / 1024;
    int beg = t * CH;
    int end = beg + CH; if (end > NN) end = NN;
    int s = 0;
    for (int i = beg; i < end; i++) s += g_cnt[i];
    tsum[t] = s;
    __syncthreads();
    for (int off = 1; off < 1024; off <<= 1) {
        int v = (t >= off) ? tsum[t - off] : 0;
        __syncthreads();
        tsum[t] += v;
        __syncthreads();
    }
    int run = (t == 0) ? 0 : tsum[t - 1];
    for (int i = beg; i < end; i++) {
        g_rowptr[i] = run; g_wr[i] = run;
        run += g_cnt[i];
    }
    if (t == 1023) g_rowptr[NN] = run;
}
__global__ void k_scatter(const int* __restrict__ src, const int* __restrict__ dst,
                          const float* __restrict__ ew) {
    int e = blockIdx.x * blockDim.x + threadIdx.x;
    if (e < NE) {
        int s = src[e], d = dst[e];
        int pos = atomicAdd(&g_wr[d], 1);
        g_col[pos] = s;
        g_val[pos] = g_dinv[s] * ew[e] * g_dinv[d];
    }
}

// ---------------- weight split/transpose: Wt[l][n][k] = split(W_l[k][n]) ----------------
__global__ void k_wconv(const float* __restrict__ Wm, const float* __restrict__ Wl) {
    int idx = blockIdx.x * blockDim.x + threadIdx.x;
    if (idx >= 7 * DD * DD) return;
    int l = idx >> 16, r = idx & 0xFFFF;
    int k = r >> 8, n = r & 255;
    const float* W = (l < 6) ? (Wm + l * DD * DD) : Wl;
    float w = W[k * DD + n];
    __nv_bfloat16 hi = __float2bfloat16(w);
    __nv_bfloat16 lo = __float2bfloat16(w - __bfloat162float(hi));
    g_wh[l * DD * DD + n * DD + k] = hi;
    g_wl[l * DD * DD + n * DD + k] = lo;
}

// ---------------- first GEMM: y = h(N,6) @ W1(6,256)  (R1-verified) ----------------
__global__ void k_gemm1(const float* __restrict__ h, const float* __restrict__ W1) {
    __shared__ float sW[6 * DD];
    __shared__ float sh[64 * 6];
    int t = threadIdx.x;
    int r0 = blockIdx.x * 64;
    for (int i = t; i < 6 * DD; i += 256) sW[i] = W1[i];
    for (int i = t; i < 64 * 6; i += 256) {
        int r = r0 + i / 6;
        sh[i] = (r < NN) ? h[r * 6 + (i % 6)] : 0.0f;
    }
    __syncthreads();
    for (int rr = 0; rr < 64; rr++) {
        int r = r0 + rr;
        if (r >= NN) break;
        float acc = 0.0f;
#pragma unroll
        for (int k = 0; k < 6; k++) acc = fmaf(sh[rr * 6 + k], sW[k * DD + t], acc);
        g_y[r * DD + t] = acc;
    }
}

// ---------------- BN apply + leaky + bf16 split: z -> (ah, al) ----------------
__global__ void __launch_bounds__(256) k_convert() {
    int idx = blockIdx.x * blockDim.x + threadIdx.x;
    if (idx >= NN * DD / 4) return;
    float4 v = *(const float4*)&g_z[idx * 4];
    int c = (idx * 4) & (DD - 1);
    float f[4] = {v.x, v.y, v.z, v.w};
    unsigned short hs[4], ls[4];
#pragma unroll
    for (int j = 0; j < 4; j++) {
        float x = fmaf(f[j], g_a[c + j], g_b2[c + j]);
        x = (x >= 0.f) ? x : SLOPE * x;
        __nv_bfloat16 hi = __float2bfloat16(x);
        __nv_bfloat16 lo = __float2bfloat16(x - __bfloat162float(hi));
        hs[j] = *(unsigned short*)&hi;
        ls[j] = *(unsigned short*)&lo;
    }
    uint2 hp, lp;
    hp.x = (uint32_t)hs[0] | ((uint32_t)hs[1] << 16);
    hp.y = (uint32_t)hs[2] | ((uint32_t)hs[3] << 16);
    lp.x = (uint32_t)ls[0] | ((uint32_t)ls[1] << 16);
    lp.y = (uint32_t)ls[2] | ((uint32_t)ls[3] << 16);
    *(uint2*)&g_ah[idx * 4] = hp;
    *(uint2*)&g_al[idx * 4] = lp;
}

// ---------------- HMMA GEMM (direct-lds fragments; weights via layer index) ----------------
#define KP 40
__global__ void __launch_bounds__(256, 1) k_mma(int layer) {
    __shared__ __nv_bfloat16 sAh[128 * KP];
    __shared__ __nv_bfloat16 sAl[128 * KP];
    __shared__ __nv_bfloat16 sBh[128 * KP];
    __shared__ __nv_bfloat16 sBl[128 * KP];
    const __nv_bfloat16* __restrict__ wh = g_wh + (size_t)layer * DD * DD;  // device-side symbol
    const __nv_bfloat16* __restrict__ wl = g_wl + (size_t)layer * DD * DD;
    const int t = threadIdx.x;
    const int w = t >> 5, lane = t & 31;
    const int gid = lane >> 2, tig = lane & 3;
    const int r0 = blockIdx.x * 128, c0 = blockIdx.y * 128;
    const int wm = (w >> 2) * 64, wn = (w & 3) * 32;
    const int lr = t >> 1, lq0 = (t & 1) * 2;

    float acc[4][4][4] = {};
    uint4 pAh[2], pAl[2], pBh[2], pBl[2];

    auto gload = [&](int k0) {
        int arow = r0 + lr;
        bool ok = arow < NN;
        const uint4* ah = (const uint4*)(g_ah + (size_t)arow * DD + k0);
        const uint4* al = (const uint4*)(g_al + (size_t)arow * DD + k0);
        const uint4* bh = (const uint4*)(wh + (size_t)(c0 + lr) * DD + k0);
        const uint4* bl = (const uint4*)(wl + (size_t)(c0 + lr) * DD + k0);
#pragma unroll
        for (int qq = 0; qq < 2; qq++) {
            int q = lq0 + qq;
            pAh[qq] = ok ? ah[q] : make_uint4(0, 0, 0, 0);
            pAl[qq] = ok ? al[q] : make_uint4(0, 0, 0, 0);
            pBh[qq] = bh[q];
            pBl[qq] = bl[q];
        }
    };
    auto sstore = [&]() {
#pragma unroll
        for (int qq = 0; qq < 2; qq++) {
            int q = lq0 + qq;
            *(uint4*)&sAh[lr * KP + q * 8] = pAh[qq];
            *(uint4*)&sAl[lr * KP + q * 8] = pAl[qq];
            *(uint4*)&sBh[lr * KP + q * 8] = pBh[qq];
            *(uint4*)&sBl[lr * KP + q * 8] = pBl[qq];
        }
    };

    gload(0);
    sstore();
    __syncthreads();

#pragma unroll 1
    for (int kt = 0; kt < 8; kt++) {
        if (kt < 7) gload((kt + 1) * 32);
#pragma unroll
        for (int kk = 0; kk < 2; kk++) {
            const int kb = kk * 16 + 2 * tig;
            uint32_t Ah[4][4], Al[4][4];
#pragma unroll
            for (int mf = 0; mf < 4; mf++) {
                int rb = (wm + mf * 16 + gid) * KP;
                Ah[mf][0] = *(const uint32_t*)&sAh[rb + kb];
                Ah[mf][1] = *(const uint32_t*)&sAh[rb + 8 * KP + kb];
                Ah[mf][2] = *(const uint32_t*)&sAh[rb + kb + 8];
                Ah[mf][3] = *(const uint32_t*)&sAh[rb + 8 * KP + kb + 8];
                Al[mf][0] = *(const uint32_t*)&sAl[rb + kb];
                Al[mf][1] = *(const uint32_t*)&sAl[rb + 8 * KP + kb];
                Al[mf][2] = *(const uint32_t*)&sAl[rb + kb + 8];
                Al[mf][3] = *(const uint32_t*)&sAl[rb + 8 * KP + kb + 8];
            }
            uint32_t Bh[2][4], Bl[2][4];
#pragma unroll
            for (int nb = 0; nb < 2; nb++) {
                int nbase = (wn + nb * 16 + gid) * KP;
                Bh[nb][0] = *(const uint32_t*)&sBh[nbase + kb];
                Bh[nb][1] = *(const uint32_t*)&sBh[nbase + kb + 8];
                Bh[nb][2] = *(const uint32_t*)&sBh[nbase + 8 * KP + kb];
                Bh[nb][3] = *(const uint32_t*)&sBh[nbase + 8 * KP + kb + 8];
                Bl[nb][0] = *(const uint32_t*)&sBl[nbase + kb];
                Bl[nb][1] = *(const uint32_t*)&sBl[nbase + kb + 8];
                Bl[nb][2] = *(const uint32_t*)&sBl[nbase + 8 * KP + kb];
                Bl[nb][3] = *(const uint32_t*)&sBl[nbase + 8 * KP + kb + 8];
            }
#pragma unroll
            for (int mf = 0; mf < 4; mf++)
#pragma unroll
                for (int nb = 0; nb < 2; nb++)
#pragma unroll
                    for (int hf = 0; hf < 2; hf++) {
                        float* a4 = acc[mf][nb * 2 + hf];
                        mma16816(a4, Ah[mf], &Bh[nb][hf * 2]);
                        mma16816(a4, Ah[mf], &Bl[nb][hf * 2]);
                        mma16816(a4, Al[mf], &Bh[nb][hf * 2]);
                    }
        }
        __syncthreads();
        if (kt < 7) { sstore(); __syncthreads(); }
    }

    int tcol = tig * 2;
#pragma unroll
    for (int mf = 0; mf < 4; mf++) {
#pragma unroll
        for (int nf = 0; nf < 4; nf++) {
            int gr = r0 + wm + mf * 16 + gid;
            int gc = c0 + wn + nf * 8 + tcol;
            if (gr < NN)
                *(float2*)&g_y[(size_t)gr * DD + gc] = make_float2(acc[mf][nf][0], acc[mf][nf][1]);
            if (gr + 8 < NN)
                *(float2*)&g_y[(size_t)(gr + 8) * DD + gc] = make_float2(acc[mf][nf][2], acc[mf][nf][3]);
        }
    }
}

// ---------------- SpMM (CSR gather by dst) + bias ----------------
__global__ void __launch_bounds__(256) k_spmm(const float* __restrict__ bias,
                                              float* __restrict__ out_opt) {
    int i = blockIdx.x;
    int c = threadIdx.x;
    int beg = g_rowptr[i], end = g_rowptr[i + 1];
    float di = g_dinv[i];
    float a0 = di * di * g_y[i * DD + c], a1 = 0.f, a2 = 0.f, a3 = 0.f;
    __shared__ int   scol[256];
    __shared__ float sval[256];
    for (int p = beg; p < end; p += 256) {
        int m = end - p; if (m > 256) m = 256;
        if (c < m) { scol[c] = g_col[p + c]; sval[c] = g_val[p + c]; }
        __syncthreads();
        int j = 0;
        for (; j + 4 <= m; j += 4) {
            a0 = fmaf(sval[j],     g_y[scol[j]     * DD + c], a0);
            a1 = fmaf(sval[j + 1], g_y[scol[j + 1] * DD + c], a1);
            a2 = fmaf(sval[j + 2], g_y[scol[j + 2] * DD + c], a2);
            a3 = fmaf(sval[j + 3], g_y[scol[j + 3] * DD + c], a3);
        }
        for (; j < m; j++) a0 = fmaf(sval[j], g_y[scol[j] * DD + c], a0);
        __syncthreads();
    }
    float* o = out_opt ? out_opt : g_z;
    o[i * DD + c] = (a0 + a1) + (a2 + a3) + bias[c];
}

// ---------------- BN stats (R1-verified) ----------------
__global__ void k_zero_stats() {
    int c = threadIdx.x;
    g_sum[c] = 0.f; g_sumsq[c] = 0.f;
}
__global__ void k_stats() {
    int c = threadIdx.x;
    float s = 0.f, s2 = 0.f;
    for (int r = blockIdx.x; r < NN; r += gridDim.x) {
        float v = g_z[r * DD + c];
        s += v; s2 += v * v;
    }
    atomicAdd(&g_sum[c], s);
    atomicAdd(&g_sumsq[c], s2);
}
__global__ void k_finalize(const float* __restrict__ gamma, const float* __restrict__ beta) {
    int c = threadIdx.x;
    float mu  = g_sum[c]   * (1.0f / NN);
    float ex2 = g_sumsq[c] * (1.0f / NN);
    float var = ex2 - mu * mu;
    float a = gamma[c] * rsqrtf(var + EPSBN);
    g_a[c]  = a;
    g_b2[c] = beta[c] - mu * a;
}

// ---------------- launch ----------------
extern "C" void kernel_launch(void* const* d_in, const int* in_sizes, int n_in,
                              void* d_out, int out_size) {
    const float* h   = (const float*)d_in[0];
    const int*   ei  = (const int*)  d_in[1];
    const float* ew  = (const float*)d_in[2];
    const float* W1  = (const float*)d_in[3];
    const float* b1  = (const float*)d_in[4];
    const float* g1  = (const float*)d_in[5];
    const float* be1 = (const float*)d_in[6];
    const float* Wm  = (const float*)d_in[7];
    const float* bm  = (const float*)d_in[8];
    const float* gm  = (const float*)d_in[9];
    const float* bem = (const float*)d_in[10];
    const float* Wl  = (const float*)d_in[11];
    const float* bl  = (const float*)d_in[12];
    const int* src = ei;
    const int* dst = ei + NE;

    k_init<<<(NN + 255) / 256, 256>>>();
    k_deg<<<(NE + 255) / 256, 256>>>(dst, ew);
    k_dinv<<<(NN + 255) / 256, 256>>>();
    k_scan<<<1, 1024>>>();
    k_scatter<<<(NE + 255) / 256, 256>>>(src, dst, ew);
    k_wconv<<<(7 * DD * DD + 255) / 256, 256>>>(Wm, Wl);

    dim3 ggrid((NN + 127) / 128, 2);

    k_gemm1<<<(NN + 63) / 64, 256>>>(h, W1);
    k_spmm<<<NN, DD>>>(b1, nullptr);
    k_zero_stats<<<1, DD>>>();
    k_stats<<<256, DD>>>();
    k_finalize<<<1, DD>>>(g1, be1);

    for (int l = 0; l < 7; l++) {
        k_convert<<<(NN * DD / 4 + 255) / 256, 256>>>();
        k_mma<<<ggrid, 256>>>(l);
        if (l < 6) {
            k_spmm<<<NN, DD>>>(bm + l * DD, nullptr);
            k_zero_stats<<<1, DD>>>();
            k_stats<<<256, DD>>>();
            k_finalize<<<1, DD>>>(gm + l * DD, bem + l * DD);
        } else {
            k_spmm<<<NN, DD>>>(bl, (float*)d_out);
        }
    }
}

// round 6
// speedup vs baseline: 1.3198x; 1.0564x over previous
#include <cuda_runtime.h>
#include <cuda_bf16.h>
#include <cstdint>

#define NN 50000
#define NE 800000
#define DD 256
#define EPSBN 1e-5f
#define SLOPE 0.01f

// ---------------- static device scratch ----------------
__device__ float g_deg[NN];
__device__ float g_dinv[NN];
__device__ int   g_cnt[NN];
__device__ int   g_rowptr[NN + 1];
__device__ int   g_wr[NN];
__device__ int   g_bsum[64];
__device__ int   g_col[NE];
__device__ float g_val[NE];
__device__ float g_y[NN * DD];                 // GEMM output (fp32)
__device__ float g_z[NN * DD];                 // SpMM output (pre-BN)
__device__ __nv_bfloat16 g_ah[NN * DD];        // split activations hi
__device__ __nv_bfloat16 g_al[NN * DD];        // split activations lo
__device__ __nv_bfloat16 g_wh[7 * DD * DD];    // split transposed weights hi  [l][n][k]
__device__ __nv_bfloat16 g_wl[7 * DD * DD];    // split transposed weights lo
__device__ float g_sum[DD];
__device__ float g_sumsq[DD];
__device__ float g_a[DD];                      // BN affine scale
__device__ float g_b2[DD];                     // BN affine shift

// ---------------- PTX helpers ----------------
__device__ __forceinline__ uint32_t smem_u32(const void* p) {
    uint32_t a;
    asm("{ .reg .u64 t; cvta.to.shared.u64 t, %1; cvt.u32.u64 %0, t; }" : "=r"(a) : "l"(p));
    return a;
}
__device__ __forceinline__ void cpasync16(uint32_t dst, const void* src, int szbytes) {
    asm volatile("cp.async.cg.shared.global [%0], [%1], 16, %2;"
                 :: "r"(dst), "l"(src), "r"(szbytes) : "memory");
}
__device__ __forceinline__ void cp_commit() {
    asm volatile("cp.async.commit_group;" ::: "memory");
}
template <int N>
__device__ __forceinline__ void cp_wait() {
    asm volatile("cp.async.wait_group %0;" :: "n"(N) : "memory");
}
__device__ __forceinline__ void ldsm4(uint32_t* r, uint32_t addr) {
    asm volatile("ldmatrix.sync.aligned.m8n8.x4.shared.b16 {%0,%1,%2,%3}, [%4];"
                 : "=r"(r[0]), "=r"(r[1]), "=r"(r[2]), "=r"(r[3]) : "r"(addr));
}
__device__ __forceinline__ void mma16816(float* c, const uint32_t* a, const uint32_t* b) {
    asm volatile(
        "mma.sync.aligned.m16n8k16.row.col.f32.bf16.bf16.f32 "
        "{%0,%1,%2,%3}, {%4,%5,%6,%7}, {%8,%9}, {%0,%1,%2,%3};"
        : "+f"(c[0]), "+f"(c[1]), "+f"(c[2]), "+f"(c[3])
        : "r"(a[0]), "r"(a[1]), "r"(a[2]), "r"(a[3]), "r"(b[0]), "r"(b[1]));
}

// ---------------- preprocessing: gcn_norm + CSR build ----------------
__global__ void k_init() {
    int i = blockIdx.x * blockDim.x + threadIdx.x;
    if (i < NN) { g_deg[i] = 1.0f; g_cnt[i] = 0; }
}
__global__ void k_deg(const int* __restrict__ dst, const float* __restrict__ ew) {
    int e = blockIdx.x * blockDim.x + threadIdx.x;
    if (e < NE) {
        int d = dst[e];
        atomicAdd(&g_deg[d], ew[e]);
        atomicAdd(&g_cnt[d], 1);
    }
}
__global__ void k_dinv() {
    int i = blockIdx.x * blockDim.x + threadIdx.x;
    if (i < NN) g_dinv[i] = rsqrtf(g_deg[i]);
}

#define SBLK 64
#define SCHUNK 782   // ceil(NN/SBLK)
__global__ void k_bsum() {
    __shared__ int red[256];
    int b = blockIdx.x, t = threadIdx.x;
    int beg = b * SCHUNK, end = beg + SCHUNK;
    if (end > NN) end = NN;
    int s = 0;
    for (int i = beg + t; i < end; i += 256) s += g_cnt[i];
    red[t] = s;
    __syncthreads();
    for (int o = 128; o > 0; o >>= 1) { if (t < o) red[t] += red[t + o]; __syncthreads(); }
    if (t == 0) g_bsum[b] = red[0];
}
__global__ void k_scan2() {
    __shared__ int sh[SBLK];
    int t = threadIdx.x;
    sh[t] = g_bsum[t];
    __syncthreads();
    for (int o = 1; o < SBLK; o <<= 1) {
        int v = (t >= o) ? sh[t - o] : 0;
        __syncthreads();
        sh[t] += v;
        __syncthreads();
    }
    g_bsum[t] = (t == 0) ? 0 : sh[t - 1];
    if (t == SBLK - 1) g_rowptr[NN] = sh[SBLK - 1];
}
__global__ void k_fill() {
    __shared__ int sh[256];
    int b = blockIdx.x, t = threadIdx.x;
    int beg = b * SCHUNK, end = beg + SCHUNK;
    if (end > NN) end = NN;
    const int per = (SCHUNK + 255) / 256;
    int s0 = beg + t * per, s1 = s0 + per;
    if (s1 > end) s1 = end;
    int s = 0;
    for (int i = s0; i < s1; i++) s += g_cnt[i];
    sh[t] = s;
    __syncthreads();
    for (int o = 1; o < 256; o <<= 1) {
        int v = (t >= o) ? sh[t - o] : 0;
        __syncthreads();
        sh[t] += v;
        __syncthreads();
    }
    int run = g_bsum[b] + ((t == 0) ? 0 : sh[t - 1]);
    for (int i = s0; i < s1; i++) {
        g_rowptr[i] = run; g_wr[i] = run;
        run += g_cnt[i];
    }
}
__global__ void k_scatter(const int* __restrict__ src, const int* __restrict__ dst,
                          const float* __restrict__ ew) {
    int e = blockIdx.x * blockDim.x + threadIdx.x;
    if (e < NE) {
        int s = src[e], d = dst[e];
        int pos = atomicAdd(&g_wr[d], 1);
        g_col[pos] = s;
        g_val[pos] = g_dinv[s] * ew[e] * g_dinv[d];
    }
}

// ---------------- weight split/transpose: Wt[l][n][k] = split(W_l[k][n]) ----------------
__global__ void k_wconv(const float* __restrict__ Wm, const float* __restrict__ Wl) {
    int idx = blockIdx.x * blockDim.x + threadIdx.x;
    if (idx >= 7 * DD * DD) return;
    int l = idx >> 16, r = idx & 0xFFFF;
    int k = r >> 8, n = r & 255;
    const float* W = (l < 6) ? (Wm + l * DD * DD) : Wl;
    float w = W[k * DD + n];
    __nv_bfloat16 hi = __float2bfloat16(w);
    __nv_bfloat16 lo = __float2bfloat16(w - __bfloat162float(hi));
    g_wh[l * DD * DD + n * DD + k] = hi;
    g_wl[l * DD * DD + n * DD + k] = lo;
}

// ---------------- first GEMM: y = h(N,6) @ W1(6,256) ----------------
__global__ void k_gemm1(const float* __restrict__ h, const float* __restrict__ W1) {
    __shared__ float sW[6 * DD];
    __shared__ float sh[64 * 6];
    int t = threadIdx.x;
    int r0 = blockIdx.x * 64;
    for (int i = t; i < 6 * DD; i += 256) sW[i] = W1[i];
    for (int i = t; i < 64 * 6; i += 256) {
        int r = r0 + i / 6;
        sh[i] = (r < NN) ? h[r * 6 + (i % 6)] : 0.0f;
    }
    __syncthreads();
    for (int rr = 0; rr < 64; rr++) {
        int r = r0 + rr;
        if (r >= NN) break;
        float acc = 0.0f;
#pragma unroll
        for (int k = 0; k < 6; k++) acc = fmaf(sh[rr * 6 + k], sW[k * DD + t], acc);
        g_y[r * DD + t] = acc;
    }
}

// ---------------- BN apply + leaky + bf16 split: z -> (ah, al) ----------------
__global__ void __launch_bounds__(256) k_convert() {
    int idx = blockIdx.x * blockDim.x + threadIdx.x;
    if (idx >= NN * DD / 4) return;
    float4 v = *(const float4*)&g_z[idx * 4];
    int c = (idx * 4) & (DD - 1);
    float f[4] = {v.x, v.y, v.z, v.w};
    unsigned short hs[4], ls[4];
#pragma unroll
    for (int j = 0; j < 4; j++) {
        float x = fmaf(f[j], g_a[c + j], g_b2[c + j]);
        x = (x >= 0.f) ? x : SLOPE * x;
        __nv_bfloat16 hi = __float2bfloat16(x);
        __nv_bfloat16 lo = __float2bfloat16(x - __bfloat162float(hi));
        hs[j] = *(unsigned short*)&hi;
        ls[j] = *(unsigned short*)&lo;
    }
    uint2 hp, lp;
    hp.x = (uint32_t)hs[0] | ((uint32_t)hs[1] << 16);
    hp.y = (uint32_t)hs[2] | ((uint32_t)hs[3] << 16);
    lp.x = (uint32_t)ls[0] | ((uint32_t)ls[1] << 16);
    lp.y = (uint32_t)ls[2] | ((uint32_t)ls[3] << 16);
    *(uint2*)&g_ah[idx * 4] = hp;
    *(uint2*)&g_al[idx * 4] = lp;
}

// ---------------- HMMA GEMM v3: 128x256 tile, 3-stage cp.async, ldmatrix ----------------
// smem stage layout (80B row pitch): Ah[128] | Al[128] | Bh[256] | Bl[256]
#define KPB 80
#define S_AH 0
#define S_AL (128 * KPB)                // 10240
#define S_BH (2 * 128 * KPB)            // 20480
#define S_BL (S_BH + 256 * KPB)         // 40960
#define STAGE_B (S_BL + 256 * KPB)      // 61440
#define NSTAGE 3
#define MMA_SMEM (STAGE_B * NSTAGE)     // 184320

__global__ void __launch_bounds__(256, 1) k_mma(int layer) {
    extern __shared__ __align__(128) char smem[];
    const uint32_t sb = smem_u32(smem);
    const __nv_bfloat16* __restrict__ wh = g_wh + (size_t)layer * DD * DD;
    const __nv_bfloat16* __restrict__ wl = g_wl + (size_t)layer * DD * DD;
    const int t = threadIdx.x;
    const int w = t >> 5, lane = t & 31;
    const int gid = lane >> 2, tig = lane & 3;
    const int r0 = blockIdx.x * 128;
    const int wm = (w >> 2) * 64, wn = (w & 3) * 64;

    auto load_stage = [&](int kt) {
        uint32_t base = sb + (kt % NSTAGE) * STAGE_B;
        int k0 = kt * 32;
        // A: 1024 chunks (row 0..127, q 0..3, tensor 0..1), 4 per thread
#pragma unroll
        for (int rep = 0; rep < 4; rep++) {
            int i = t + rep * 256;
            int row = i & 127, q = (i >> 7) & 3, tn = i >> 9;
            int gr = r0 + row;
            const __nv_bfloat16* src = (tn ? g_al : g_ah) + (size_t)gr * DD + k0 + q * 8;
            uint32_t doff = (tn ? S_AL : S_AH) + row * KPB + q * 16;
            cpasync16(base + doff, src, gr < NN ? 16 : 0);
        }
        // B: 2048 chunks (row 0..255, q 0..3, tensor 0..1), 8 per thread
#pragma unroll
        for (int rep = 0; rep < 8; rep++) {
            int i = t + rep * 256;
            int row = i & 255, q = (i >> 8) & 3, tn = i >> 10;
            const __nv_bfloat16* src = (tn ? wl : wh) + (size_t)row * DD + k0 + q * 8;
            uint32_t doff = (tn ? S_BL : S_BH) + row * KPB + q * 16;
            cpasync16(base + doff, src, 16);
        }
        cp_commit();
    };

    float acc[4][8][4] = {};

    load_stage(0);
    load_stage(1);

    // ldmatrix lane addressing (verified equal to R5 direct-lds layout)
    const int a_row = lane & 15;
    const int a_kb = (lane >> 4) * 16;
    const int b_row = ((lane >> 4) << 3) + (lane & 7);
    const int b_kb = ((lane >> 3) & 1) * 16;

#pragma unroll 1
    for (int kt = 0; kt < 8; kt++) {
        cp_wait<1>();
        __syncthreads();
        if (kt + 2 < 8) load_stage(kt + 2);
        else cp_commit();                      // empty group keeps wait<1> uniform
        uint32_t base = sb + (kt % NSTAGE) * STAGE_B;
#pragma unroll
        for (int kk = 0; kk < 2; kk++) {
            uint32_t koff = kk * 32;
            uint32_t Ah[4][4], Al[4][4];
#pragma unroll
            for (int mf = 0; mf < 4; mf++) {
                uint32_t addr = base + S_AH + (wm + mf * 16 + a_row) * KPB + koff + a_kb;
                ldsm4(Ah[mf], addr);
                ldsm4(Al[mf], addr + (S_AL - S_AH));
            }
#pragma unroll
            for (int nb = 0; nb < 4; nb++) {
                uint32_t Bh[4], Bl[4];
                uint32_t addr = base + S_BH + (wn + nb * 16 + b_row) * KPB + koff + b_kb;
                ldsm4(Bh, addr);
                ldsm4(Bl, addr + (S_BL - S_BH));
#pragma unroll
                for (int mf = 0; mf < 4; mf++)
#pragma unroll
                    for (int hf = 0; hf < 2; hf++) {
                        float* a4 = acc[mf][nb * 2 + hf];
                        mma16816(a4, Ah[mf], &Bh[hf * 2]);
                        mma16816(a4, Ah[mf], &Bl[hf * 2]);
                        mma16816(a4, Al[mf], &Bh[hf * 2]);
                    }
            }
        }
        __syncthreads();
    }

    // epilogue
    int tcol = tig * 2;
#pragma unroll
    for (int mf = 0; mf < 4; mf++) {
#pragma unroll
        for (int nf = 0; nf < 8; nf++) {
            int gr = r0 + wm + mf * 16 + gid;
            int gc = wn + nf * 8 + tcol;
            if (gr < NN)
                *(float2*)&g_y[(size_t)gr * DD + gc] = make_float2(acc[mf][nf][0], acc[mf][nf][1]);
            if (gr + 8 < NN)
                *(float2*)&g_y[(size_t)(gr + 8) * DD + gc] = make_float2(acc[mf][nf][2], acc[mf][nf][3]);
        }
    }
}

// ---------------- SpMM (CSR gather by dst) + bias ----------------
__global__ void __launch_bounds__(256) k_spmm(const float* __restrict__ bias,
                                              float* __restrict__ out_opt) {
    int i = blockIdx.x;
    int c = threadIdx.x;
    int beg = g_rowptr[i], end = g_rowptr[i + 1];
    float di = g_dinv[i];
    float a0 = di * di * g_y[i * DD + c], a1 = 0.f, a2 = 0.f, a3 = 0.f;
    __shared__ int   scol[256];
    __shared__ float sval[256];
    for (int p = beg; p < end; p += 256) {
        int m = end - p; if (m > 256) m = 256;
        if (c < m) { scol[c] = g_col[p + c]; sval[c] = g_val[p + c]; }
        __syncthreads();
        int j = 0;
        for (; j + 4 <= m; j += 4) {
            a0 = fmaf(sval[j],     g_y[scol[j]     * DD + c], a0);
            a1 = fmaf(sval[j + 1], g_y[scol[j + 1] * DD + c], a1);
            a2 = fmaf(sval[j + 2], g_y[scol[j + 2] * DD + c], a2);
            a3 = fmaf(sval[j + 3], g_y[scol[j + 3] * DD + c], a3);
        }
        for (; j < m; j++) a0 = fmaf(sval[j], g_y[scol[j] * DD + c], a0);
        __syncthreads();
    }
    float* o = out_opt ? out_opt : g_z;
    o[i * DD + c] = (a0 + a1) + (a2 + a3) + bias[c];
}

// ---------------- BN stats ----------------
__global__ void k_stats() {
    int c = threadIdx.x;
    float s = 0.f, s2 = 0.f;
    for (int r = blockIdx.x; r < NN; r += gridDim.x) {
        float v = g_z[r * DD + c];
        s += v; s2 += v * v;
    }
    atomicAdd(&g_sum[c], s);
    atomicAdd(&g_sumsq[c], s2);
}
__global__ void k_finalize(const float* __restrict__ gamma, const float* __restrict__ beta) {
    int c = threadIdx.x;
    float mu  = g_sum[c]   * (1.0f / NN);
    float ex2 = g_sumsq[c] * (1.0f / NN);
    float var = ex2 - mu * mu;
    float a = gamma[c] * rsqrtf(var + EPSBN);
    g_a[c]  = a;
    g_b2[c] = beta[c] - mu * a;
    g_sum[c] = 0.f;        // reset for next layer / replay (replay-invariant)
    g_sumsq[c] = 0.f;
}

// ---------------- launch ----------------
extern "C" void kernel_launch(void* const* d_in, const int* in_sizes, int n_in,
                              void* d_out, int out_size) {
    const float* h   = (const float*)d_in[0];
    const int*   ei  = (const int*)  d_in[1];
    const float* ew  = (const float*)d_in[2];
    const float* W1  = (const float*)d_in[3];
    const float* b1  = (const float*)d_in[4];
    const float* g1  = (const float*)d_in[5];
    const float* be1 = (const float*)d_in[6];
    const float* Wm  = (const float*)d_in[7];
    const float* bm  = (const float*)d_in[8];
    const float* gm  = (const float*)d_in[9];
    const float* bem = (const float*)d_in[10];
    const float* Wl  = (const float*)d_in[11];
    const float* bl  = (const float*)d_in[12];
    const int* src = ei;
    const int* dst = ei + NE;

    cudaFuncSetAttribute(k_mma, cudaFuncAttributeMaxDynamicSharedMemorySize, MMA_SMEM);

    k_init<<<(NN + 255) / 256, 256>>>();
    k_deg<<<(NE + 255) / 256, 256>>>(dst, ew);
    k_dinv<<<(NN + 255) / 256, 256>>>();
    k_bsum<<<SBLK, 256>>>();
    k_scan2<<<1, SBLK>>>();
    k_fill<<<SBLK, 256>>>();
    k_scatter<<<(NE + 255) / 256, 256>>>(src, dst, ew);
    k_wconv<<<(7 * DD * DD + 255) / 256, 256>>>(Wm, Wl);

    int gtiles = (NN + 127) / 128;

    k_gemm1<<<(NN + 63) / 64, 256>>>(h, W1);
    k_spmm<<<NN, DD>>>(b1, nullptr);
    k_stats<<<256, DD>>>();
    k_finalize<<<1, DD>>>(g1, be1);

    for (int l = 0; l < 7; l++) {
        k_convert<<<(NN * DD / 4 + 255) / 256, 256>>>();
        k_mma<<<gtiles, 256, MMA_SMEM>>>(l);
        if (l < 6) {
            k_spmm<<<NN, DD>>>(bm + l * DD, nullptr);
            k_stats<<<256, DD>>>();
            k_finalize<<<1, DD>>>(gm + l * DD, bem + l * DD);
        } else {
            k_spmm<<<NN, DD>>>(bl, (float*)d_out);
        }
    }
}